// round 1
// baseline (speedup 1.0000x reference)
#include <cuda_runtime.h>
#include <cstdint>
#include <cstddef>

// ---------------- problem constants ----------------
#define BB   4
#define TT   2048
#define HIDD 2048
#define HH   16
#define DKK  128
#define DVV  128
#define NBT  (BB*TT)           // 8192 rows
static constexpr float SCALE_F = 0.08838834764831845f;  // 128^-0.5
static constexpr float EPS_F   = 1e-5f;

// ---------------- scratch (device globals; no allocation allowed) ----------------
// 10 buffers of [8192, 2048] + beta [8192,16]
#define BUFE ((size_t)NBT * HIDD)
__device__ float g_scratch[BUFE * 10 + (size_t)NBT * HH];

__device__ __forceinline__ float sigmoidf_(float x) { return 1.f / (1.f + expf(-x)); }

// ======================================================================
// SGEMM: C[M,N] = A[M,K] @ B[K,N], row-major fp32.
// 128x128 tile, BK=16, 256 threads, 8x8 per thread, double-buffered smem.
// epi: 0 = none, 1 = sigmoid(acc + bias[col]) (bias may be null -> 0)
// Requires M%128==0, N%128==0, K%16==0 (true for all our calls).
// ======================================================================
__global__ void __launch_bounds__(256, 2) sgemm_kernel(
    const float* __restrict__ A, const float* __restrict__ B,
    const float* __restrict__ bias, float* __restrict__ C,
    int M, int N, int K, int epi)
{
    __shared__ float As[2][16][128];
    __shared__ float Bs[2][16][128];

    const int tid = threadIdx.x;
    const int tx  = tid & 15;          // col group
    const int ty  = tid >> 4;          // row group
    const int bm  = blockIdx.y * 128;
    const int bn  = blockIdx.x * 128;

    // A loaders: rows (arow, arow+64), cols acol..acol+3 within the k-tile
    const int arow = tid >> 2;          // 0..63
    const int acol = (tid & 3) << 2;    // 0,4,8,12
    // B loaders: rows (brow, brow+8), 4 cols at bcol
    const int brow = tid >> 5;          // 0..7
    const int bcol = (tid & 31) << 2;   // 0..124

    const float* Ap = A + (size_t)(bm + arow) * K + acol;
    const float* Bp = B + (size_t)brow * N + bn + bcol;

    // initial tile -> buffer 0
    {
        float4 a0 = *(const float4*)Ap;
        float4 a1 = *(const float4*)(Ap + (size_t)64 * K);
        float4 b0 = *(const float4*)Bp;
        float4 b1 = *(const float4*)(Bp + (size_t)8 * N);
        As[0][acol+0][arow]    = a0.x; As[0][acol+1][arow]    = a0.y;
        As[0][acol+2][arow]    = a0.z; As[0][acol+3][arow]    = a0.w;
        As[0][acol+0][arow+64] = a1.x; As[0][acol+1][arow+64] = a1.y;
        As[0][acol+2][arow+64] = a1.z; As[0][acol+3][arow+64] = a1.w;
        *(float4*)&Bs[0][brow][bcol]   = b0;
        *(float4*)&Bs[0][brow+8][bcol] = b1;
    }
    __syncthreads();

    float acc[8][8];
    #pragma unroll
    for (int i = 0; i < 8; i++)
        #pragma unroll
        for (int j = 0; j < 8; j++) acc[i][j] = 0.f;

    const int ntiles = K >> 4;
    for (int kt = 0; kt < ntiles; kt++) {
        const int cur = kt & 1;
        float4 na0, na1, nb0, nb1;
        const bool pre = (kt + 1 < ntiles);
        if (pre) {
            const float* ap = Ap + (kt + 1) * 16;
            na0 = *(const float4*)ap;
            na1 = *(const float4*)(ap + (size_t)64 * K);
            const float* bp = B + (size_t)((kt + 1) * 16 + brow) * N + bn + bcol;
            nb0 = *(const float4*)bp;
            nb1 = *(const float4*)(bp + (size_t)8 * N);
        }
        #pragma unroll
        for (int kk = 0; kk < 16; kk++) {
            float ar[8], br[8];
            *(float4*)&ar[0] = *(const float4*)&As[cur][kk][ty * 8];
            *(float4*)&ar[4] = *(const float4*)&As[cur][kk][ty * 8 + 4];
            *(float4*)&br[0] = *(const float4*)&Bs[cur][kk][tx * 4];
            *(float4*)&br[4] = *(const float4*)&Bs[cur][kk][64 + tx * 4];
            #pragma unroll
            for (int i = 0; i < 8; i++)
                #pragma unroll
                for (int j = 0; j < 8; j++)
                    acc[i][j] += ar[i] * br[j];
        }
        if (pre) {
            const int nxt = cur ^ 1;
            As[nxt][acol+0][arow]    = na0.x; As[nxt][acol+1][arow]    = na0.y;
            As[nxt][acol+2][arow]    = na0.z; As[nxt][acol+3][arow]    = na0.w;
            As[nxt][acol+0][arow+64] = na1.x; As[nxt][acol+1][arow+64] = na1.y;
            As[nxt][acol+2][arow+64] = na1.z; As[nxt][acol+3][arow+64] = na1.w;
            *(float4*)&Bs[nxt][brow][bcol]   = nb0;
            *(float4*)&Bs[nxt][brow+8][bcol] = nb1;
        }
        __syncthreads();
    }

    // epilogue
    const int c0 = bn + tx * 4;
    const int c1 = bn + 64 + tx * 4;
    #pragma unroll
    for (int i = 0; i < 8; i++) {
        const int row = bm + ty * 8 + i;
        float* crow = C + (size_t)row * N;
        float4 o0 = make_float4(acc[i][0], acc[i][1], acc[i][2], acc[i][3]);
        float4 o1 = make_float4(acc[i][4], acc[i][5], acc[i][6], acc[i][7]);
        if (epi == 1) {
            float bv0 = 0, bv1 = 0, bv2 = 0, bv3 = 0, bv4 = 0, bv5 = 0, bv6 = 0, bv7 = 0;
            if (bias) {
                bv0 = bias[c0]; bv1 = bias[c0+1]; bv2 = bias[c0+2]; bv3 = bias[c0+3];
                bv4 = bias[c1]; bv5 = bias[c1+1]; bv6 = bias[c1+2]; bv7 = bias[c1+3];
            }
            o0.x = sigmoidf_(o0.x + bv0); o0.y = sigmoidf_(o0.y + bv1);
            o0.z = sigmoidf_(o0.z + bv2); o0.w = sigmoidf_(o0.w + bv3);
            o1.x = sigmoidf_(o1.x + bv4); o1.y = sigmoidf_(o1.y + bv5);
            o1.z = sigmoidf_(o1.z + bv6); o1.w = sigmoidf_(o1.w + bv7);
        }
        *(float4*)&crow[c0] = o0;
        *(float4*)&crow[c1] = o1;
    }
}

// ======================================================================
// beta = sigmoid(x @ Wb + bb), Wb: [2048,16]  out: [8192,16]
// 256 threads = 16 rows x 16 cols per block
// ======================================================================
__global__ void beta_kernel(const float* __restrict__ x, const float* __restrict__ Wb,
                            const float* __restrict__ bb, float* __restrict__ out)
{
    const int row = blockIdx.x * 16 + (threadIdx.x >> 4);
    const int col = threadIdx.x & 15;
    const float* xr = x + (size_t)row * HIDD;
    float acc = 0.f;
    for (int k = 0; k < HIDD; k += 4) {
        float4 xv = *(const float4*)(xr + k);
        acc += xv.x * Wb[(k + 0) * HH + col];
        acc += xv.y * Wb[(k + 1) * HH + col];
        acc += xv.z * Wb[(k + 2) * HH + col];
        acc += xv.w * Wb[(k + 3) * HH + col];
    }
    out[(size_t)row * HH + col] = sigmoidf_(acc + bb[col]);
}

// ======================================================================
// causal depthwise conv (K=4) + bias + SiLU (+scale).  u,y: [B*T, 2048]
// ======================================================================
__global__ void conv_silu_kernel(const float* __restrict__ u, const float* __restrict__ w,
                                 const float* __restrict__ bias, float* __restrict__ y,
                                 float scale)
{
    const size_t gid = (size_t)blockIdx.x * blockDim.x + threadIdx.x;  // over NBT*2048
    const int c  = (int)(gid & (HIDD - 1));
    const size_t bt = gid >> 11;
    const int t  = (int)(bt & (TT - 1));
    float acc = bias[c];
    const float* up = u + gid;
    #pragma unroll
    for (int j = 0; j < 4; j++) {
        const int ttc = t - 3 + j;
        if (ttc >= 0) acc += w[c * 4 + j] * up[(ptrdiff_t)(j - 3) * HIDD];
    }
    const float sv = acc * sigmoidf_(acc);   // silu
    y[gid] = sv * scale;
}

// ======================================================================
// Delta-rule scan. State row S[v,:] is independent across v, so we
// parallelize over (b, h, v-half): 128 blocks x 256 threads.
// Thread = (v_local in 0..63, chunk c in 0..3 of 32 k-dims), state in regs.
// Double-buffered smem staging of k/q/v/a/beta, one barrier per step.
// ======================================================================
__global__ void __launch_bounds__(256, 1) scan_kernel(
    const float* __restrict__ q, const float* __restrict__ k,
    const float* __restrict__ v, const float* __restrict__ a,
    const float* __restrict__ beta, float* __restrict__ o)
{
    __shared__ float ksm[2][4 * 36];   // stride 36: conflict-free + 16B aligned
    __shared__ float qsm[2][4 * 36];
    __shared__ float vsm[2][64];
    __shared__ float gsm[2][64];
    __shared__ float bsm[2];

    const int blk  = blockIdx.x;        // 0..127
    const int b    = blk >> 5;
    const int h    = (blk >> 1) & 15;
    const int half = blk & 1;

    const int tid = threadIdx.x;
    const int vl  = tid >> 2;           // 0..63
    const int c   = tid & 3;            // k-chunk
    const int vg  = half * 64 + vl;

    const int lc     = tid & 127;
    const int lsm    = (lc >> 5) * 36 + (lc & 31);

    const size_t baseQK = (size_t)b * TT * HIDD + h * DKK;
    const size_t baseVA = (size_t)b * TT * HIDD + h * DVV;

    float s[32];
    #pragma unroll
    for (int i = 0; i < 32; i++) s[i] = 0.f;

    // prologue: stage t=0 into buffer 0
    if (tid < 128) ksm[0][lsm] = k[baseQK + lc];
    else           qsm[0][lsm] = q[baseQK + lc];
    if (tid < 64)            vsm[0][tid]       = v[baseVA + half * 64 + tid];
    else if (tid < 128)      gsm[0][tid - 64]  = a[baseVA + half * 64 + (tid - 64)];
    if (tid == 0)            bsm[0] = beta[(size_t)b * TT * HH + h];

    for (int t = 0; t < TT; t++) {
        const int buf = t & 1;
        __syncthreads();

        const float* kb = &ksm[buf][c * 36];
        const float* qb = &qsm[buf][c * 36];
        const float av = gsm[buf][vl];
        const float vt = vsm[buf][vl];
        const float bt = bsm[buf];

        float kf[32];
        #pragma unroll
        for (int i = 0; i < 32; i += 4) {
            float4 k4 = *(const float4*)(kb + i);
            kf[i] = k4.x; kf[i+1] = k4.y; kf[i+2] = k4.z; kf[i+3] = k4.w;
        }
        float sk = 0.f;
        #pragma unroll
        for (int i = 0; i < 32; i++) sk += s[i] * kf[i];
        sk += __shfl_xor_sync(0xffffffffu, sk, 1);
        sk += __shfl_xor_sync(0xffffffffu, sk, 2);

        const float d = bt * (sk - vt);

        float op = 0.f;
        #pragma unroll
        for (int i = 0; i < 32; i += 4) {
            float4 q4 = *(const float4*)(qb + i);
            s[i]   = av * s[i]   - d * kf[i];   op += s[i]   * q4.x;
            s[i+1] = av * s[i+1] - d * kf[i+1]; op += s[i+1] * q4.y;
            s[i+2] = av * s[i+2] - d * kf[i+2]; op += s[i+2] * q4.z;
            s[i+3] = av * s[i+3] - d * kf[i+3]; op += s[i+3] * q4.w;
        }
        op += __shfl_xor_sync(0xffffffffu, op, 1);
        op += __shfl_xor_sync(0xffffffffu, op, 2);
        if (c == 0)
            o[(size_t)(b * TT + t) * HIDD + h * DKK + vg] = op;

        // prefetch t+1 into the other buffer (safe: barrier at loop top)
        if (t + 1 < TT) {
            const size_t off = (size_t)(t + 1) * HIDD;
            const int nb = buf ^ 1;
            if (tid < 128) ksm[nb][lsm] = k[baseQK + off + lc];
            else           qsm[nb][lsm] = q[baseQK + off + lc];
            if (tid < 64)        vsm[nb][tid]      = v[baseVA + off + half * 64 + tid];
            else if (tid < 128)  gsm[nb][tid - 64] = a[baseVA + off + half * 64 + (tid - 64)];
            if (tid == 0)        bsm[nb] = beta[(size_t)(b * TT + t + 1) * HH + h];
        }
    }
}

// ======================================================================
// LayerNorm over DV=128 + gate.  warp per (b,t,h) row of 128.
// ======================================================================
__global__ void ln_gate_kernel(const float* __restrict__ o, const float* __restrict__ g,
                               const float* __restrict__ lnw, const float* __restrict__ lnb,
                               float* __restrict__ out)
{
    const int gw   = (int)(((size_t)blockIdx.x * blockDim.x + threadIdx.x) >> 5);
    const int lane = threadIdx.x & 31;
    const size_t base = (size_t)gw * 128 + lane * 4;
    float4 x = *(const float4*)(o + base);
    float s  = x.x + x.y + x.z + x.w;
    float ss = x.x * x.x + x.y * x.y + x.z * x.z + x.w * x.w;
    #pragma unroll
    for (int m = 16; m > 0; m >>= 1) {
        s  += __shfl_xor_sync(0xffffffffu, s,  m);
        ss += __shfl_xor_sync(0xffffffffu, ss, m);
    }
    const float mu  = s * (1.f / 128.f);
    const float var = ss * (1.f / 128.f) - mu * mu;
    const float inv = rsqrtf(var + EPS_F);
    const float4 wv = *(const float4*)(lnw + lane * 4);
    const float4 bv = *(const float4*)(lnb + lane * 4);
    const float4 gv = *(const float4*)(g + base);
    float4 r;
    r.x = ((x.x - mu) * inv * wv.x + bv.x) * gv.x;
    r.y = ((x.y - mu) * inv * wv.y + bv.y) * gv.y;
    r.z = ((x.z - mu) * inv * wv.z + bv.z) * gv.z;
    r.w = ((x.w - mu) * inv * wv.w + bv.w) * gv.w;
    *(float4*)(out + base) = r;
}

// ======================================================================
// launch
// ======================================================================
extern "C" void kernel_launch(void* const* d_in, const int* in_sizes, int n_in,
                              void* d_out, int out_size)
{
    const float* x       = (const float*)d_in[0];
    const float* Wq      = (const float*)d_in[1];
    const float* Wk      = (const float*)d_in[2];
    const float* Wv      = (const float*)d_in[3];
    const float* Wa      = (const float*)d_in[4];
    const float* ba      = (const float*)d_in[5];
    const float* Wb      = (const float*)d_in[6];
    const float* bb      = (const float*)d_in[7];
    const float* Wg      = (const float*)d_in[8];
    const float* Wo      = (const float*)d_in[9];
    const float* qconv_w = (const float*)d_in[10];
    const float* qconv_b = (const float*)d_in[11];
    const float* kconv_w = (const float*)d_in[12];
    const float* kconv_b = (const float*)d_in[13];
    const float* vconv_w = (const float*)d_in[14];
    const float* vconv_b = (const float*)d_in[15];
    const float* ln_w    = (const float*)d_in[16];
    const float* ln_b    = (const float*)d_in[17];

    void* sp = nullptr;
    cudaGetSymbolAddress(&sp, g_scratch);
    float* base = (float*)sp;
    float* d_qpre  = base + 0 * BUFE;
    float* d_kpre  = base + 1 * BUFE;
    float* d_vpre  = base + 2 * BUFE;
    float* d_q     = base + 3 * BUFE;
    float* d_k     = base + 4 * BUFE;
    float* d_v     = base + 5 * BUFE;
    float* d_a     = base + 6 * BUFE;
    float* d_g     = base + 7 * BUFE;
    float* d_o     = base + 8 * BUFE;
    float* d_gated = base + 9 * BUFE;
    float* d_beta  = base + 10 * BUFE;

    const dim3 gg(HIDD / 128, NBT / 128);   // (16, 64)

    sgemm_kernel<<<gg, 256>>>(x, Wq, nullptr, d_qpre, NBT, HIDD, HIDD, 0);
    sgemm_kernel<<<gg, 256>>>(x, Wk, nullptr, d_kpre, NBT, HIDD, HIDD, 0);
    sgemm_kernel<<<gg, 256>>>(x, Wv, nullptr, d_vpre, NBT, HIDD, HIDD, 0);
    sgemm_kernel<<<gg, 256>>>(x, Wa, ba,      d_a,    NBT, HIDD, HIDD, 1);
    sgemm_kernel<<<gg, 256>>>(x, Wg, nullptr, d_g,    NBT, HIDD, HIDD, 1);
    beta_kernel<<<NBT / 16, 256>>>(x, Wb, bb, d_beta);

    const int convBlocks = (int)((size_t)NBT * HIDD / 256);
    conv_silu_kernel<<<convBlocks, 256>>>(d_qpre, qconv_w, qconv_b, d_q, 1.f);
    conv_silu_kernel<<<convBlocks, 256>>>(d_kpre, kconv_w, kconv_b, d_k, SCALE_F);
    conv_silu_kernel<<<convBlocks, 256>>>(d_vpre, vconv_w, vconv_b, d_v, 1.f);

    scan_kernel<<<BB * HH * 2, 256>>>(d_q, d_k, d_v, d_a, d_beta, d_o);

    ln_gate_kernel<<<(NBT * HH) / 8, 256>>>(d_o, d_g, ln_w, ln_b, d_gated);

    sgemm_kernel<<<gg, 256>>>(d_gated, Wo, nullptr, (float*)d_out, NBT, HIDD, HIDD, 0);

    (void)in_sizes; (void)n_in; (void)out_size;
}

// round 4
// speedup vs baseline: 1.6949x; 1.6949x over previous
#include <cuda_runtime.h>
#include <cuda_bf16.h>
#include <cstdint>
#include <cstddef>

// ---------------- problem constants ----------------
#define BB   4
#define TT   2048
#define HIDD 2048
#define HH   16
#define DKK  128
#define DVV  128
#define NBT  (BB*TT)           // 8192 rows
static constexpr float SCALE_F = 0.08838834764831845f;  // 128^-0.5
static constexpr float EPS_F   = 1e-5f;

// ---------------- scratch (device globals; no allocation allowed) ----------------
#define BUFE ((size_t)NBT * HIDD)      // 16.78M elems
#define WE   ((size_t)HIDD * HIDD)     // 4.19M elems
__device__ float         g_scratch[BUFE * 9 + (size_t)NBT * HH];
__device__ __nv_bfloat16 g_bf[BUFE * 4 + WE * 12];

__device__ __forceinline__ float sigmoidf_(float x) { return 1.f / (1.f + expf(-x)); }

__device__ __forceinline__ uint32_t smem_u32(const void* p) {
    uint32_t a;
    asm("{ .reg .u64 t; cvta.to.shared.u64 t, %1; cvt.u32.u64 %0, t; }" : "=r"(a) : "l"(p));
    return a;
}
__device__ __forceinline__ void cp16(uint32_t dst, const void* src) {
    asm volatile("cp.async.cg.shared.global [%0], [%1], 16;" :: "r"(dst), "l"(src));
}
__device__ __forceinline__ void cp_commit() {
    asm volatile("cp.async.commit_group;" ::: "memory");
}
__device__ __forceinline__ void ldsm4(uint32_t* r, uint32_t addr) {
    asm volatile("ldmatrix.sync.aligned.m8n8.x4.shared.b16 {%0,%1,%2,%3}, [%4];"
                 : "=r"(r[0]), "=r"(r[1]), "=r"(r[2]), "=r"(r[3]) : "r"(addr));
}
__device__ __forceinline__ void mma16816(float* c, const uint32_t* a, uint32_t b0, uint32_t b1) {
    asm volatile("mma.sync.aligned.m16n8k16.row.col.f32.bf16.bf16.f32 "
                 "{%0,%1,%2,%3}, {%4,%5,%6,%7}, {%8,%9}, {%0,%1,%2,%3};"
                 : "+f"(c[0]), "+f"(c[1]), "+f"(c[2]), "+f"(c[3])
                 : "r"(a[0]), "r"(a[1]), "r"(a[2]), "r"(a[3]), "r"(b0), "r"(b1));
}

// ======================================================================
// mma.sync GEMM: C[8192,2048] = A[8192,2048] @ W[2048,2048], bf16x3 split.
// A as (Ahi, Alo) [M,K] bf16 row-major; W as (Bhi, Blo) [N,K] bf16 (= W^T).
// CTA tile 128x128, BK=64, 8 warps (warp tile 32x64), 2-stage cp.async.
// epi: 0 = none, 1 = sigmoid(acc + bias[col]) (bias may be null)
// ======================================================================
#define GK     2048
#define BK     64
#define NCH    (GK / BK)          // 32
#define SM_AH  0
#define SM_AL  (16 * 1024)
#define SM_BH  (32 * 1024)
#define SM_BL  (48 * 1024)
#define STAGE  (64 * 1024)
#define SMEM_GEMM (2 * STAGE)     // 131072

__global__ void __launch_bounds__(256, 1)
gemm_bf16x3_kernel(const __nv_bfloat16* __restrict__ Ahi, const __nv_bfloat16* __restrict__ Alo,
                   const __nv_bfloat16* __restrict__ Bhi, const __nv_bfloat16* __restrict__ Blo,
                   const float* __restrict__ bias, float* __restrict__ C, int epi)
{
    extern __shared__ __align__(1024) char sm[];
    const uint32_t smb = smem_u32(sm);

    const int tid  = threadIdx.x;
    const int wid  = tid >> 5;
    const int lane = tid & 31;
    const int bm   = blockIdx.y * 128;
    const int bn   = blockIdx.x * 128;
    const int wm   = wid & 3;       // M group (4 x 32 rows)
    const int wn   = wid >> 2;      // N group (2 x 64 cols)

    const __nv_bfloat16* Ah = Ahi + (size_t)bm * GK;
    const __nv_bfloat16* Al = Alo + (size_t)bm * GK;
    const __nv_bfloat16* Bh = Bhi + (size_t)bn * GK;
    const __nv_bfloat16* Bl = Blo + (size_t)bn * GK;

    // loader indexing: 1024 16B-chunks per 128x64 tile, 4 per thread
    const int lrow = tid >> 1;                 // unused pattern; use per-i below

    auto prefetch = [&](int st, int k0) {
        const uint32_t base = smb + st * STAGE;
        #pragma unroll
        for (int i = 0; i < 4; i++) {
            const int s   = tid + 256 * i;
            const int row = s >> 3, seg = s & 7;
            const uint32_t sw = row * 128 + ((seg * 16) ^ ((row & 7) << 4));
            const size_t go = (size_t)row * GK + k0 + seg * 8;
            cp16(base + SM_AH + sw, Ah + go);
            cp16(base + SM_AL + sw, Al + go);
            cp16(base + SM_BH + sw, Bh + go);
            cp16(base + SM_BL + sw, Bl + go);
        }
        cp_commit();
    };

    prefetch(0, 0);
    prefetch(1, BK);

    float acc[2][8][4];
    #pragma unroll
    for (int i = 0; i < 2; i++)
        #pragma unroll
        for (int j = 0; j < 8; j++)
            #pragma unroll
            for (int q = 0; q < 4; q++) acc[i][j][q] = 0.f;

    // per-lane ldmatrix address pieces
    const int l16  = lane & 15;
    const uint32_t xorv = (uint32_t)((lane & 7) << 4);
    const uint32_t chalf = (uint32_t)((lane >> 4) * 16);     // byte offset of k-halves
    uint32_t arow128[2], brow128[4];
    #pragma unroll
    for (int mt = 0; mt < 2; mt++) arow128[mt] = (uint32_t)((wm * 32 + mt * 16 + l16) * 128);
    #pragma unroll
    for (int nt = 0; nt < 4; nt++) brow128[nt] = (uint32_t)((wn * 64 + nt * 16 + l16) * 128);

    for (int c = 0; c < NCH; c++) {
        if (c + 1 < NCH) asm volatile("cp.async.wait_group 1;" ::: "memory");
        else             asm volatile("cp.async.wait_group 0;" ::: "memory");
        __syncthreads();

        const uint32_t base = smb + (c & 1) * STAGE;
        #pragma unroll
        for (int kk = 0; kk < 4; kk++) {
            const uint32_t koff = kk * 32 + chalf;
            uint32_t ah[2][4], al[2][4];
            #pragma unroll
            for (int mt = 0; mt < 2; mt++) {
                const uint32_t off = arow128[mt] + (koff ^ xorv);
                ldsm4(ah[mt], base + SM_AH + off);
                ldsm4(al[mt], base + SM_AL + off);
            }
            #pragma unroll
            for (int nt = 0; nt < 4; nt++) {
                const uint32_t boff = brow128[nt] + (koff ^ xorv);
                uint32_t bh[4], bl[4];
                ldsm4(bh, base + SM_BH + boff);
                ldsm4(bl, base + SM_BL + boff);
                #pragma unroll
                for (int mt = 0; mt < 2; mt++) {
                    mma16816(acc[mt][nt * 2],     ah[mt], bh[0], bh[2]);
                    mma16816(acc[mt][nt * 2 + 1], ah[mt], bh[1], bh[3]);
                    mma16816(acc[mt][nt * 2],     al[mt], bh[0], bh[2]);
                    mma16816(acc[mt][nt * 2 + 1], al[mt], bh[1], bh[3]);
                    mma16816(acc[mt][nt * 2],     ah[mt], bl[0], bl[2]);
                    mma16816(acc[mt][nt * 2 + 1], ah[mt], bl[1], bl[3]);
                }
            }
        }
        __syncthreads();
        if (c + 2 < NCH) prefetch(c & 1, (c + 2) * BK);
    }

    // epilogue
    #pragma unroll
    for (int mt = 0; mt < 2; mt++) {
        const int r0 = bm + wm * 32 + mt * 16 + (lane >> 2);
        #pragma unroll
        for (int j = 0; j < 8; j++) {
            const int cc = bn + wn * 64 + j * 8 + (lane & 3) * 2;
            float v0 = acc[mt][j][0], v1 = acc[mt][j][1];
            float v2 = acc[mt][j][2], v3 = acc[mt][j][3];
            if (epi == 1) {
                const float b0 = bias ? bias[cc]     : 0.f;
                const float b1 = bias ? bias[cc + 1] : 0.f;
                v0 = sigmoidf_(v0 + b0); v1 = sigmoidf_(v1 + b1);
                v2 = sigmoidf_(v2 + b0); v3 = sigmoidf_(v3 + b1);
            }
            *(float2*)(C + (size_t)r0 * HIDD + cc)       = make_float2(v0, v1);
            *(float2*)(C + (size_t)(r0 + 8) * HIDD + cc) = make_float2(v2, v3);
        }
    }
    (void)lrow;
}

// ======================================================================
// elementwise fp32 -> (bf16 hi, bf16 lo)
// ======================================================================
__global__ void split_kernel(const float* __restrict__ in,
                             __nv_bfloat16* __restrict__ hi, __nv_bfloat16* __restrict__ lo)
{
    const size_t i = (size_t)blockIdx.x * blockDim.x + threadIdx.x;
    const float v = in[i];
    const __nv_bfloat16 h = __float2bfloat16(v);
    hi[i] = h;
    lo[i] = __float2bfloat16(v - __bfloat162float(h));
}

// ======================================================================
// W [K=2048, N=2048] f32 -> Whi^T, Wlo^T [N, K] bf16
// ======================================================================
__global__ void transpose_split_kernel(const float* __restrict__ W,
                                       __nv_bfloat16* __restrict__ hi, __nv_bfloat16* __restrict__ lo)
{
    __shared__ float tile[32][33];
    const int tx = threadIdx.x, ty = threadIdx.y;     // (32, 8)
    const int x0 = blockIdx.x * 32, y0 = blockIdx.y * 32;
    #pragma unroll
    for (int j = 0; j < 32; j += 8)
        tile[ty + j][tx] = W[(size_t)(y0 + ty + j) * HIDD + x0 + tx];
    __syncthreads();
    #pragma unroll
    for (int j = 0; j < 32; j += 8) {
        const float v = tile[tx][ty + j];
        const __nv_bfloat16 h = __float2bfloat16(v);
        const size_t o = (size_t)(x0 + ty + j) * HIDD + y0 + tx;
        hi[o] = h;
        lo[o] = __float2bfloat16(v - __bfloat162float(h));
    }
}

// ======================================================================
// beta = sigmoid(x @ Wb + bb)
// ======================================================================
__global__ void beta_kernel(const float* __restrict__ x, const float* __restrict__ Wb,
                            const float* __restrict__ bb, float* __restrict__ out)
{
    const int row = blockIdx.x * 16 + (threadIdx.x >> 4);
    const int col = threadIdx.x & 15;
    const float* xr = x + (size_t)row * HIDD;
    float acc = 0.f;
    for (int k = 0; k < HIDD; k += 4) {
        float4 xv = *(const float4*)(xr + k);
        acc += xv.x * Wb[(k + 0) * HH + col];
        acc += xv.y * Wb[(k + 1) * HH + col];
        acc += xv.z * Wb[(k + 2) * HH + col];
        acc += xv.w * Wb[(k + 3) * HH + col];
    }
    out[(size_t)row * HH + col] = sigmoidf_(acc + bb[col]);
}

// ======================================================================
// causal depthwise conv (K=4) + bias + SiLU (+scale)
// ======================================================================
__global__ void conv_silu_kernel(const float* __restrict__ u, const float* __restrict__ w,
                                 const float* __restrict__ bias, float* __restrict__ y,
                                 float scale)
{
    const size_t gid = (size_t)blockIdx.x * blockDim.x + threadIdx.x;
    const int c  = (int)(gid & (HIDD - 1));
    const size_t bt = gid >> 11;
    const int t  = (int)(bt & (TT - 1));
    float acc = bias[c];
    const float* up = u + gid;
    #pragma unroll
    for (int j = 0; j < 4; j++) {
        const int ttc = t - 3 + j;
        if (ttc >= 0) acc += w[c * 4 + j] * up[(ptrdiff_t)(j - 3) * HIDD];
    }
    const float sv = acc * sigmoidf_(acc);
    y[gid] = sv * scale;
}

// ======================================================================
// Delta-rule scan (unchanged from R1)
// ======================================================================
__global__ void __launch_bounds__(256, 1) scan_kernel(
    const float* __restrict__ q, const float* __restrict__ k,
    const float* __restrict__ v, const float* __restrict__ a,
    const float* __restrict__ beta, float* __restrict__ o)
{
    __shared__ float ksm[2][4 * 36];
    __shared__ float qsm[2][4 * 36];
    __shared__ float vsm[2][64];
    __shared__ float gsm[2][64];
    __shared__ float bsm[2];

    const int blk  = blockIdx.x;
    const int b    = blk >> 5;
    const int h    = (blk >> 1) & 15;
    const int half = blk & 1;

    const int tid = threadIdx.x;
    const int vl  = tid >> 2;
    const int c   = tid & 3;
    const int vg  = half * 64 + vl;

    const int lc  = tid & 127;
    const int lsm = (lc >> 5) * 36 + (lc & 31);

    const size_t baseQK = (size_t)b * TT * HIDD + h * DKK;
    const size_t baseVA = (size_t)b * TT * HIDD + h * DVV;

    float s[32];
    #pragma unroll
    for (int i = 0; i < 32; i++) s[i] = 0.f;

    if (tid < 128) ksm[0][lsm] = k[baseQK + lc];
    else           qsm[0][lsm] = q[baseQK + lc];
    if (tid < 64)            vsm[0][tid]      = v[baseVA + half * 64 + tid];
    else if (tid < 128)      gsm[0][tid - 64] = a[baseVA + half * 64 + (tid - 64)];
    if (tid == 0)            bsm[0] = beta[(size_t)b * TT * HH + h];

    for (int t = 0; t < TT; t++) {
        const int buf = t & 1;
        __syncthreads();

        const float* kb = &ksm[buf][c * 36];
        const float* qb = &qsm[buf][c * 36];
        const float av = gsm[buf][vl];
        const float vt = vsm[buf][vl];
        const float bt = bsm[buf];

        float kf[32];
        #pragma unroll
        for (int i = 0; i < 32; i += 4) {
            float4 k4 = *(const float4*)(kb + i);
            kf[i] = k4.x; kf[i+1] = k4.y; kf[i+2] = k4.z; kf[i+3] = k4.w;
        }
        float sk = 0.f;
        #pragma unroll
        for (int i = 0; i < 32; i++) sk += s[i] * kf[i];
        sk += __shfl_xor_sync(0xffffffffu, sk, 1);
        sk += __shfl_xor_sync(0xffffffffu, sk, 2);

        const float d = bt * (sk - vt);

        float op = 0.f;
        #pragma unroll
        for (int i = 0; i < 32; i += 4) {
            float4 q4 = *(const float4*)(qb + i);
            s[i]   = av * s[i]   - d * kf[i];   op += s[i]   * q4.x;
            s[i+1] = av * s[i+1] - d * kf[i+1]; op += s[i+1] * q4.y;
            s[i+2] = av * s[i+2] - d * kf[i+2]; op += s[i+2] * q4.z;
            s[i+3] = av * s[i+3] - d * kf[i+3]; op += s[i+3] * q4.w;
        }
        op += __shfl_xor_sync(0xffffffffu, op, 1);
        op += __shfl_xor_sync(0xffffffffu, op, 2);
        if (c == 0)
            o[(size_t)(b * TT + t) * HIDD + h * DKK + vg] = op;

        if (t + 1 < TT) {
            const size_t off = (size_t)(t + 1) * HIDD;
            const int nb = buf ^ 1;
            if (tid < 128) ksm[nb][lsm] = k[baseQK + off + lc];
            else           qsm[nb][lsm] = q[baseQK + off + lc];
            if (tid < 64)        vsm[nb][tid]      = v[baseVA + off + half * 64 + tid];
            else if (tid < 128)  gsm[nb][tid - 64] = a[baseVA + off + half * 64 + (tid - 64)];
            if (tid == 0)        bsm[nb] = beta[(size_t)(b * TT + t + 1) * HH + h];
        }
    }
}

// ======================================================================
// LayerNorm over DV=128 + gate, output split to bf16 hi/lo (final GEMM A)
// ======================================================================
__global__ void ln_gate_kernel(const float* __restrict__ o, const float* __restrict__ g,
                               const float* __restrict__ lnw, const float* __restrict__ lnb,
                               __nv_bfloat16* __restrict__ ghi, __nv_bfloat16* __restrict__ glo)
{
    const int gw   = (int)(((size_t)blockIdx.x * blockDim.x + threadIdx.x) >> 5);
    const int lane = threadIdx.x & 31;
    const size_t base = (size_t)gw * 128 + lane * 4;
    float4 x = *(const float4*)(o + base);
    float s  = x.x + x.y + x.z + x.w;
    float ss = x.x * x.x + x.y * x.y + x.z * x.z + x.w * x.w;
    #pragma unroll
    for (int m = 16; m > 0; m >>= 1) {
        s  += __shfl_xor_sync(0xffffffffu, s,  m);
        ss += __shfl_xor_sync(0xffffffffu, ss, m);
    }
    const float mu  = s * (1.f / 128.f);
    const float var = ss * (1.f / 128.f) - mu * mu;
    const float inv = rsqrtf(var + EPS_F);
    const float4 wv = *(const float4*)(lnw + lane * 4);
    const float4 bv = *(const float4*)(lnb + lane * 4);
    const float4 gv = *(const float4*)(g + base);
    float r[4];
    r[0] = ((x.x - mu) * inv * wv.x + bv.x) * gv.x;
    r[1] = ((x.y - mu) * inv * wv.y + bv.y) * gv.y;
    r[2] = ((x.z - mu) * inv * wv.z + bv.z) * gv.z;
    r[3] = ((x.w - mu) * inv * wv.w + bv.w) * gv.w;
    __nv_bfloat16 h[4], l[4];
    #pragma unroll
    for (int i = 0; i < 4; i++) {
        h[i] = __float2bfloat16(r[i]);
        l[i] = __float2bfloat16(r[i] - __bfloat162float(h[i]));
    }
    *(__nv_bfloat162*)(ghi + base)     = __nv_bfloat162(h[0], h[1]);
    *(__nv_bfloat162*)(ghi + base + 2) = __nv_bfloat162(h[2], h[3]);
    *(__nv_bfloat162*)(glo + base)     = __nv_bfloat162(l[0], l[1]);
    *(__nv_bfloat162*)(glo + base + 2) = __nv_bfloat162(l[2], l[3]);
}

// ======================================================================
// launch
// ======================================================================
extern "C" void kernel_launch(void* const* d_in, const int* in_sizes, int n_in,
                              void* d_out, int out_size)
{
    const float* x       = (const float*)d_in[0];
    const float* Wq      = (const float*)d_in[1];
    const float* Wk      = (const float*)d_in[2];
    const float* Wv      = (const float*)d_in[3];
    const float* Wa      = (const float*)d_in[4];
    const float* ba      = (const float*)d_in[5];
    const float* Wb      = (const float*)d_in[6];
    const float* bb      = (const float*)d_in[7];
    const float* Wg      = (const float*)d_in[8];
    const float* Wo      = (const float*)d_in[9];
    const float* qconv_w = (const float*)d_in[10];
    const float* qconv_b = (const float*)d_in[11];
    const float* kconv_w = (const float*)d_in[12];
    const float* kconv_b = (const float*)d_in[13];
    const float* vconv_w = (const float*)d_in[14];
    const float* vconv_b = (const float*)d_in[15];
    const float* ln_w    = (const float*)d_in[16];
    const float* ln_b    = (const float*)d_in[17];

    void* sp = nullptr;
    cudaGetSymbolAddress(&sp, g_scratch);
    float* fb = (float*)sp;
    float* d_qpre = fb + 0 * BUFE;
    float* d_kpre = fb + 1 * BUFE;
    float* d_vpre = fb + 2 * BUFE;
    float* d_q    = fb + 3 * BUFE;
    float* d_k    = fb + 4 * BUFE;
    float* d_v    = fb + 5 * BUFE;
    float* d_a    = fb + 6 * BUFE;
    float* d_g    = fb + 7 * BUFE;
    float* d_o    = fb + 8 * BUFE;
    float* d_beta = fb + 9 * BUFE;

    void* bp = nullptr;
    cudaGetSymbolAddress(&bp, g_bf);
    __nv_bfloat16* hb = (__nv_bfloat16*)bp;
    __nv_bfloat16* xhi = hb + 0 * BUFE;
    __nv_bfloat16* xlo = hb + 1 * BUFE;
    __nv_bfloat16* ghi = hb + 2 * BUFE;
    __nv_bfloat16* glo = hb + 3 * BUFE;
    __nv_bfloat16* wt  = hb + 4 * BUFE;       // 12 x WE: (hi,lo) x {q,k,v,a,g,o}
    __nv_bfloat16* Wq_hi = wt + 0 * WE, *Wq_lo = wt + 1 * WE;
    __nv_bfloat16* Wk_hi = wt + 2 * WE, *Wk_lo = wt + 3 * WE;
    __nv_bfloat16* Wv_hi = wt + 4 * WE, *Wv_lo = wt + 5 * WE;
    __nv_bfloat16* Wa_hi = wt + 6 * WE, *Wa_lo = wt + 7 * WE;
    __nv_bfloat16* Wg_hi = wt + 8 * WE, *Wg_lo = wt + 9 * WE;
    __nv_bfloat16* Wo_hi = wt + 10 * WE, *Wo_lo = wt + 11 * WE;

    cudaFuncSetAttribute(gemm_bf16x3_kernel,
                         cudaFuncAttributeMaxDynamicSharedMemorySize, SMEM_GEMM);

    // operand prep
    split_kernel<<<(int)(BUFE / 256), 256>>>(x, xhi, xlo);
    const dim3 tg(HIDD / 32, HIDD / 32), tb(32, 8);
    transpose_split_kernel<<<tg, tb>>>(Wq, Wq_hi, Wq_lo);
    transpose_split_kernel<<<tg, tb>>>(Wk, Wk_hi, Wk_lo);
    transpose_split_kernel<<<tg, tb>>>(Wv, Wv_hi, Wv_lo);
    transpose_split_kernel<<<tg, tb>>>(Wa, Wa_hi, Wa_lo);
    transpose_split_kernel<<<tg, tb>>>(Wg, Wg_hi, Wg_lo);
    transpose_split_kernel<<<tg, tb>>>(Wo, Wo_hi, Wo_lo);

    // 5 big projections on tensor cores (mma.sync)
    const dim3 gg(HIDD / 128, NBT / 128);     // (16, 64)
    gemm_bf16x3_kernel<<<gg, 256, SMEM_GEMM>>>(xhi, xlo, Wq_hi, Wq_lo, nullptr, d_qpre, 0);
    gemm_bf16x3_kernel<<<gg, 256, SMEM_GEMM>>>(xhi, xlo, Wk_hi, Wk_lo, nullptr, d_kpre, 0);
    gemm_bf16x3_kernel<<<gg, 256, SMEM_GEMM>>>(xhi, xlo, Wv_hi, Wv_lo, nullptr, d_vpre, 0);
    gemm_bf16x3_kernel<<<gg, 256, SMEM_GEMM>>>(xhi, xlo, Wa_hi, Wa_lo, ba,      d_a,    1);
    gemm_bf16x3_kernel<<<gg, 256, SMEM_GEMM>>>(xhi, xlo, Wg_hi, Wg_lo, nullptr, d_g,    1);

    beta_kernel<<<NBT / 16, 256>>>(x, Wb, bb, d_beta);

    const int convBlocks = (int)((size_t)NBT * HIDD / 256);
    conv_silu_kernel<<<convBlocks, 256>>>(d_qpre, qconv_w, qconv_b, d_q, 1.f);
    conv_silu_kernel<<<convBlocks, 256>>>(d_kpre, kconv_w, kconv_b, d_k, SCALE_F);
    conv_silu_kernel<<<convBlocks, 256>>>(d_vpre, vconv_w, vconv_b, d_v, 1.f);

    scan_kernel<<<BB * HH * 2, 256>>>(d_q, d_k, d_v, d_a, d_beta, d_o);

    ln_gate_kernel<<<(NBT * HH) / 8, 256>>>(d_o, d_g, ln_w, ln_b, ghi, glo);

    gemm_bf16x3_kernel<<<gg, 256, SMEM_GEMM>>>(ghi, glo, Wo_hi, Wo_lo, nullptr, (float*)d_out, 0);

    (void)in_sizes; (void)n_in; (void)out_size;
}